// round 2
// baseline (speedup 1.0000x reference)
#include <cuda_runtime.h>
#include <math_constants.h>

#define BB   4
#define TT   1024
#define EE   1024
#define HH   16
#define DD   64
#define BTC  4096                       // B*T
#define BHTD (BB*HH*TT*DD)              // 4,194,304

// Scratch (static device globals; no runtime allocation)
__device__ float g_q[2 * BHTD];
__device__ float g_k[2 * BHTD];
__device__ float g_v[2 * BHTD];
__device__ float g_ctx[2 * BTC * EE];

// ---------------------------------------------------------------------------
// Tiled SGEMM: C[m,n] = sum_k A[m,k] * W[n,k]   (A: M x 1024, W: N x 1024)
// BM=BN=128, BK=16, 256 threads, 8x8 per thread.
// mode 0: QKV projection — scatter epilogue into g_q/g_k/g_v[stream] ([b,h,t,d])
//         (column e of Wqkv decodes as e = di*48 + ki*16 + h)
// mode 1: output projection — A = g_ctx[stream], plain store to C
// ---------------------------------------------------------------------------
__global__ void __launch_bounds__(256) sgemm_kernel(
    const float* __restrict__ A, const float* __restrict__ W,
    float* __restrict__ C, int N, int mode, int stream)
{
    __shared__ float As[16][132];
    __shared__ float Ws[16][132];
    if (mode == 1) A = g_ctx + (size_t)stream * (BTC * EE);

    const int K = 1024;
    const int tid   = threadIdx.x;
    const int mBase = blockIdx.y << 7;
    const int nBase = blockIdx.x << 7;

    const int lrow = tid >> 2;          // 0..63
    const int lk   = (tid & 3) << 2;    // 0,4,8,12
    const int trow = (tid >> 4) << 3;   // 0..120
    const int tcol = (tid & 15) << 3;   // 0..120

    float acc[8][8];
#pragma unroll
    for (int i = 0; i < 8; i++)
#pragma unroll
        for (int j = 0; j < 8; j++) acc[i][j] = 0.f;

    for (int k0 = 0; k0 < K; k0 += 16) {
#pragma unroll
        for (int rr = 0; rr < 2; rr++) {
            int r = lrow + (rr << 6);
            float4 av = *(const float4*)&A[(size_t)(mBase + r) * K + k0 + lk];
            As[lk+0][r] = av.x; As[lk+1][r] = av.y;
            As[lk+2][r] = av.z; As[lk+3][r] = av.w;
            float4 wv = *(const float4*)&W[(size_t)(nBase + r) * K + k0 + lk];
            Ws[lk+0][r] = wv.x; Ws[lk+1][r] = wv.y;
            Ws[lk+2][r] = wv.z; Ws[lk+3][r] = wv.w;
        }
        __syncthreads();
#pragma unroll
        for (int kk = 0; kk < 16; kk++) {
            float a[8], b[8];
            *(float4*)&a[0] = *(const float4*)&As[kk][trow];
            *(float4*)&a[4] = *(const float4*)&As[kk][trow + 4];
            *(float4*)&b[0] = *(const float4*)&Ws[kk][tcol];
            *(float4*)&b[4] = *(const float4*)&Ws[kk][tcol + 4];
#pragma unroll
            for (int i = 0; i < 8; i++)
#pragma unroll
                for (int j = 0; j < 8; j++)
                    acc[i][j] += a[i] * b[j];
        }
        __syncthreads();
    }

    if (mode == 0) {
        float* qo = g_q + (size_t)stream * BHTD;
        float* ko = g_k + (size_t)stream * BHTD;
        float* vo = g_v + (size_t)stream * BHTD;
#pragma unroll
        for (int i = 0; i < 8; i++) {
            int m = mBase + trow + i;
            int b = m >> 10, t = m & 1023;
#pragma unroll
            for (int j = 0; j < 8; j++) {
                int n   = nBase + tcol + j;
                int di  = n / 48;
                int rem = n - di * 48;
                int ki  = rem >> 4;
                int h   = rem & 15;
                int idx = ((b * HH + h) * TT + t) * DD + di;
                float val = acc[i][j];
                if      (ki == 0) qo[idx] = val;
                else if (ki == 1) ko[idx] = val;
                else              vo[idx] = val;
            }
        }
    } else {
#pragma unroll
        for (int i = 0; i < 8; i++) {
            int m = mBase + trow + i;
            *(float4*)&C[(size_t)m * N + nBase + tcol] =
                make_float4(acc[i][0], acc[i][1], acc[i][2], acc[i][3]);
            *(float4*)&C[(size_t)m * N + nBase + tcol + 4] =
                make_float4(acc[i][4], acc[i][5], acc[i][6], acc[i][7]);
        }
    }
}

// ---------------------------------------------------------------------------
// Flash cross-attention. grid = (T/64, B*H, 2 output streams), 256 threads.
// Output stream o=0: xo = softmax(q2·k1/8)·v1 ; o=1: yo = softmax(q1·k2/8)·v2.
// Writes g_ctx[o] in [b, t, h*64+d] layout.
// Thread (ty,tx) of a 16x16 grid owns a 4x4 S/O sub-tile. Row stats reduced
// over the 16 lanes sharing a ty (contiguous half-warp) via shfl.xor.
// ---------------------------------------------------------------------------
#define ASTR 68

__global__ void __launch_bounds__(256) attn_kernel()
{
    extern __shared__ float sm[];
    float* Qs = sm;
    float* Ks = sm + 64 * ASTR;
    float* Vs = sm + 2 * 64 * ASTR;
    float* Ps = sm + 3 * 64 * ASTR;

    const int tid   = threadIdx.x;
    const int o     = blockIdx.z;
    const int bh    = blockIdx.y;
    const int qRow0 = blockIdx.x << 6;

    const float* qptr = g_q + (size_t)(1 - o) * BHTD + (size_t)bh * (TT * DD);
    const float* kptr = g_k + (size_t)o       * BHTD + (size_t)bh * (TT * DD);
    const float* vptr = g_v + (size_t)o       * BHTD + (size_t)bh * (TT * DD);

    const int ty4 = (tid >> 4) << 2;
    const int tx4 = (tid & 15) << 2;

    // Load the 64x64 Q tile
#pragma unroll
    for (int it = 0; it < 4; it++) {
        int idx = tid + (it << 8);
        int r   = idx >> 4;
        int c4  = (idx & 15) << 2;
        *(float4*)&Qs[r * ASTR + c4] =
            *(const float4*)&qptr[(qRow0 + r) * DD + c4];
    }

    float m_run[4], l_run[4], oacc[4][4];
#pragma unroll
    for (int i = 0; i < 4; i++) {
        m_run[i] = -CUDART_INF_F;
        l_run[i] = 0.f;
#pragma unroll
        for (int j = 0; j < 4; j++) oacc[i][j] = 0.f;
    }

    const float sc = 0.125f * 1.4426950408889634f;  // 1/sqrt(64) * log2(e)

    for (int t0 = 0; t0 < TT; t0 += 64) {
#pragma unroll
        for (int it = 0; it < 4; it++) {
            int idx = tid + (it << 8);
            int r   = idx >> 4;
            int c4  = (idx & 15) << 2;
            *(float4*)&Ks[r * ASTR + c4] = *(const float4*)&kptr[(t0 + r) * DD + c4];
            *(float4*)&Vs[r * ASTR + c4] = *(const float4*)&vptr[(t0 + r) * DD + c4];
        }
        __syncthreads();   // also covers the initial Q tile on the first pass

        float s[4][4];
#pragma unroll
        for (int i = 0; i < 4; i++)
#pragma unroll
            for (int j = 0; j < 4; j++) s[i][j] = 0.f;

#pragma unroll
        for (int d = 0; d < 64; d += 4) {
            float qf[4][4], kf[4][4];
#pragma unroll
            for (int i = 0; i < 4; i++) {
                float4 t = *(const float4*)&Qs[(ty4 + i) * ASTR + d];
                qf[i][0] = t.x; qf[i][1] = t.y; qf[i][2] = t.z; qf[i][3] = t.w;
            }
#pragma unroll
            for (int j = 0; j < 4; j++) {
                float4 t = *(const float4*)&Ks[(tx4 + j) * ASTR + d];
                kf[j][0] = t.x; kf[j][1] = t.y; kf[j][2] = t.z; kf[j][3] = t.w;
            }
#pragma unroll
            for (int i = 0; i < 4; i++)
#pragma unroll
                for (int j = 0; j < 4; j++)
#pragma unroll
                    for (int dd = 0; dd < 4; dd++)
                        s[i][j] += qf[i][dd] * kf[j][dd];
        }

        // online softmax (log2 domain)
#pragma unroll
        for (int i = 0; i < 4; i++) {
#pragma unroll
            for (int j = 0; j < 4; j++) s[i][j] *= sc;
            float mt = fmaxf(fmaxf(s[i][0], s[i][1]), fmaxf(s[i][2], s[i][3]));
#pragma unroll
            for (int off = 8; off; off >>= 1)
                mt = fmaxf(mt, __shfl_xor_sync(0xffffffffu, mt, off));
            float mnew = fmaxf(m_run[i], mt);
            float corr = exp2f(m_run[i] - mnew);
            m_run[i] = mnew;
            float rs = 0.f;
#pragma unroll
            for (int j = 0; j < 4; j++) {
                float p = exp2f(s[i][j] - mnew);
                s[i][j] = p;
                rs += p;
            }
#pragma unroll
            for (int off = 8; off; off >>= 1)
                rs += __shfl_xor_sync(0xffffffffu, rs, off);
            l_run[i] = l_run[i] * corr + rs;
#pragma unroll
            for (int j = 0; j < 4; j++) oacc[i][j] *= corr;
        }

        // stage P through shared, then O += P @ V
#pragma unroll
        for (int i = 0; i < 4; i++)
            *(float4*)&Ps[(ty4 + i) * ASTR + tx4] =
                make_float4(s[i][0], s[i][1], s[i][2], s[i][3]);
        __syncthreads();

#pragma unroll
        for (int cc = 0; cc < 64; cc += 4) {
            float vf[4][4];
#pragma unroll
            for (int r = 0; r < 4; r++) {
                float4 t = *(const float4*)&Vs[(cc + r) * ASTR + tx4];
                vf[r][0] = t.x; vf[r][1] = t.y; vf[r][2] = t.z; vf[r][3] = t.w;
            }
#pragma unroll
            for (int i = 0; i < 4; i++) {
                float4 p = *(const float4*)&Ps[(ty4 + i) * ASTR + cc];
#pragma unroll
                for (int j = 0; j < 4; j++)
                    oacc[i][j] += p.x * vf[0][j] + p.y * vf[1][j]
                                + p.z * vf[2][j] + p.w * vf[3][j];
            }
        }
        __syncthreads();   // protect Ks/Vs/Ps before next tile
    }

    const int b = bh >> 4;
    const int h = bh & 15;
    float* outp = g_ctx + (size_t)o * (BTC * EE);
#pragma unroll
    for (int i = 0; i < 4; i++) {
        float inv = 1.f / l_run[i];
        int row = qRow0 + ty4 + i;
        *(float4*)&outp[(size_t)(b * TT + row) * EE + h * DD + tx4] =
            make_float4(oacc[i][0] * inv, oacc[i][1] * inv,
                        oacc[i][2] * inv, oacc[i][3] * inv);
    }
}

// ---------------------------------------------------------------------------

extern "C" void kernel_launch(void* const* d_in, const int* in_sizes, int n_in,
                              void* d_out, int out_size)
{
    const float* x     = (const float*)d_in[0];
    const float* y     = (const float*)d_in[1];
    const float* Wqkv1 = (const float*)d_in[2];
    const float* Wqkv2 = (const float*)d_in[3];
    const float* Wout1 = (const float*)d_in[4];
    const float* Wout2 = (const float*)d_in[5];
    float* out = (float*)d_out;

    const int attn_smem = 4 * 64 * ASTR * (int)sizeof(float);   // 69632 B
    cudaFuncSetAttribute(attn_kernel,
                         cudaFuncAttributeMaxDynamicSharedMemorySize, attn_smem);

    dim3 blk(256);
    // QKV projections (with fused de-interleave to [b,h,t,d])
    sgemm_kernel<<<dim3(24, 32), blk>>>(x, Wqkv1, nullptr, 3072, 0, 0);
    sgemm_kernel<<<dim3(24, 32), blk>>>(y, Wqkv2, nullptr, 3072, 0, 1);
    // Cross attention (both directions in one grid)
    attn_kernel<<<dim3(16, 64, 2), blk, attn_smem>>>();
    // Output projections straight into d_out (xo@Wout1^T, then yo@Wout2^T)
    sgemm_kernel<<<dim3(8, 32), blk>>>(nullptr, Wout1, out, 1024, 1, 0);
    sgemm_kernel<<<dim3(8, 32), blk>>>(nullptr, Wout2, out + (size_t)BTC * EE, 1024, 1, 1);
}

// round 10
// speedup vs baseline: 3.5949x; 3.5949x over previous
#include <cuda_runtime.h>
#include <cstdint>
#include <math_constants.h>

#define TT 1024
#define EE 1024
#define BTC 4096
#define NQKV 3072

// ---------------- scratch ----------------
__device__ float g_xc[BTC*EE];
__device__ float g_yc[BTC*EE];
__device__ float g_w1c[NQKV*EE];
__device__ float g_w2c[NQKV*EE];
__device__ float g_wo1c[EE*EE];
__device__ float g_wo2c[EE*EE];
__device__ float g_qkv[2][(size_t)BTC*NQKV];
__device__ float g_q [2][(size_t)BTC*EE];   // [bh][t][d]   tf32 bits
__device__ float g_k [2][(size_t)BTC*EE];   // [bh][t][d]   tf32 bits
__device__ float g_vt[2][(size_t)BTC*EE];   // [bh][d][t]   tf32 bits (transposed)
__device__ float g_ctx[2][(size_t)BTC*EE];  // [b,t][h*64+d] tf32 bits

// ---------------- helpers ----------------
__device__ __forceinline__ float totf(float x){
    uint32_t u; asm("cvt.rna.tf32.f32 %0, %1;" : "=r"(u) : "f"(x));
    return __uint_as_float(u);
}
__device__ __forceinline__ float ex2(float x){
    float r; asm("ex2.approx.ftz.f32 %0, %1;" : "=f"(r) : "f"(x)); return r;
}
__device__ __forceinline__ void ldsm4(uint32_t r[4], uint32_t a){
    asm volatile("ldmatrix.sync.aligned.m8n8.x4.shared.b16 {%0,%1,%2,%3}, [%4];"
        : "=r"(r[0]),"=r"(r[1]),"=r"(r[2]),"=r"(r[3]) : "r"(a));
}
__device__ __forceinline__ void mma8(float d[4], const uint32_t a[4], const uint32_t b[2]){
    asm volatile("mma.sync.aligned.m16n8k8.row.col.f32.tf32.tf32.f32 "
        "{%0,%1,%2,%3}, {%4,%5,%6,%7}, {%8,%9}, {%0,%1,%2,%3};"
        : "+f"(d[0]),"+f"(d[1]),"+f"(d[2]),"+f"(d[3])
        : "r"(a[0]),"r"(a[1]),"r"(a[2]),"r"(a[3]),"r"(b[0]),"r"(b[1]));
}
__device__ __forceinline__ void cp16(uint32_t s, const void* g){
    asm volatile("cp.async.cg.shared.global [%0], [%1], 16;" :: "r"(s), "l"(g));
}

// ---------------- convert inputs to tf32 ----------------
__global__ void __launch_bounds__(256) cvt_kernel(const float4* __restrict__ src, int dst, int n4){
    float* dp = dst==0?g_xc: dst==1?g_yc: dst==2?g_w1c: dst==3?g_w2c: dst==4?g_wo1c: g_wo2c;
    int i = blockIdx.x*256 + threadIdx.x;
    if (i < n4){
        float4 v = src[i];
        float4 o; o.x=totf(v.x); o.y=totf(v.y); o.z=totf(v.z); o.w=totf(v.w);
        ((float4*)dp)[i] = o;
    }
}

// ---------------- TF32 GEMM: C[m][n] = sum_k A[m][k]*W[n][k] ----------------
#define ASTR 20
__global__ void __launch_bounds__(256) mm_kernel(float* __restrict__ Cout, int mode, int stream)
{
    __shared__ __align__(16) float As[2][128*ASTR];
    __shared__ __align__(16) float Bs[2][128*ASTR];
    const float *A, *W; float* C; int N;
    if (mode==0){ A = stream? g_yc : g_xc; W = stream? g_w2c : g_w1c; C = g_qkv[stream]; N = NQKV; }
    else        { A = g_ctx[stream]; W = stream? g_wo2c : g_wo1c; C = Cout; N = EE; }

    const int tid=threadIdx.x, lane=tid&31, wid=tid>>5;
    const int wm=wid>>2, wn=wid&3;                  // 2 x 4 warp grid, 64x32 tiles
    const int mBase=blockIdx.y<<7, nBase=blockIdx.x<<7;
    const int g=lane>>2, tq=lane&3, sel=lane>>3;
    const int aRow=(lane&7)+((sel&1)<<3), aCol=(sel>>1)<<2;
    const int bRow=(lane&7)+((sel>>1)<<3), bCol=(sel&1)<<2;
    uint32_t sA=(uint32_t)__cvta_generic_to_shared(As);
    uint32_t sB=(uint32_t)__cvta_generic_to_shared(Bs);
    const int lr=tid>>2, lkc=(tid&3)<<2;

    float acc[4][4][4];
#pragma unroll
    for (int i=0;i<4;i++)
#pragma unroll
        for (int j=0;j<4;j++){ acc[i][j][0]=0;acc[i][j][1]=0;acc[i][j][2]=0;acc[i][j][3]=0; }

    auto issue = [&](int buf, int k0){
        int bo = buf*(128*ASTR);
        cp16(sA + (uint32_t)((bo + lr*ASTR      + lkc)*4), &A[(size_t)(mBase+lr   )*EE + k0 + lkc]);
        cp16(sA + (uint32_t)((bo + (lr+64)*ASTR + lkc)*4), &A[(size_t)(mBase+lr+64)*EE + k0 + lkc]);
        cp16(sB + (uint32_t)((bo + lr*ASTR      + lkc)*4), &W[(size_t)(nBase+lr   )*EE + k0 + lkc]);
        cp16(sB + (uint32_t)((bo + (lr+64)*ASTR + lkc)*4), &W[(size_t)(nBase+lr+64)*EE + k0 + lkc]);
        asm volatile("cp.async.commit_group;");
    };
    auto compute = [&](int buf){
        int bo = buf*(128*ASTR);
#pragma unroll
        for (int kh=0; kh<2; kh++){
            uint32_t af[4][4], bf[4][2];
#pragma unroll
            for (int fm=0; fm<4; fm++)
                ldsm4(af[fm], sA + (uint32_t)((bo + (wm*64+fm*16+aRow)*ASTR + kh*8 + aCol)*4));
#pragma unroll
            for (int f2=0; f2<2; f2++){
                uint32_t r[4];
                ldsm4(r, sB + (uint32_t)((bo + (wn*32+f2*16+bRow)*ASTR + kh*8 + bCol)*4));
                bf[2*f2][0]=r[0]; bf[2*f2][1]=r[1]; bf[2*f2+1][0]=r[2]; bf[2*f2+1][1]=r[3];
            }
#pragma unroll
            for (int fm=0; fm<4; fm++)
#pragma unroll
                for (int fn=0; fn<4; fn++)
                    mma8(acc[fm][fn], af[fm], bf[fn]);
        }
    };

    issue(0, 0);
    asm volatile("cp.async.wait_group 0;");
    __syncthreads();
    for (int kt=0; kt<64; kt++){
        int buf = kt&1;
        if (kt<63) issue(buf^1, (kt+1)*16);
        compute(buf);
        asm volatile("cp.async.wait_group 0;");
        __syncthreads();
    }

#pragma unroll
    for (int fm=0; fm<4; fm++)
#pragma unroll
        for (int fn=0; fn<4; fn++){
            size_t r0 = (size_t)(mBase + wm*64 + fm*16 + g);
            int col = nBase + wn*32 + fn*8 + 2*tq;
            *(float2*)&C[r0*N + col]     = make_float2(acc[fm][fn][0], acc[fm][fn][1]);
            *(float2*)&C[(r0+8)*N + col] = make_float2(acc[fm][fn][2], acc[fm][fn][3]);
        }
}

// ---------------- de-interleave qkv rows -> q/k (bh,t,d) + v transposed (bh,d,t) ----------------
// column e of qkv decodes as e = d*48 + ki*16 + h
__global__ void __launch_bounds__(256) deint_kernel(int stream){
    __shared__ float sm[3136];                       // element e stored at e + e/48 (stride 49)
    const int row=blockIdx.x, b=row>>10, t=row&1023, tid=threadIdx.x;
    const float4* src=(const float4*)(g_qkv[stream]+(size_t)row*NQKV);
    for (int i=tid;i<768;i+=256){
        float4 v=src[i]; int e=i<<2; int base=e + e/48;
        sm[base]=v.x; sm[base+1]=v.y; sm[base+2]=v.z; sm[base+3]=v.w;
    }
    __syncthreads();
    const int e0=tid<<2, h=e0>>6, d0=e0&63;
    const size_t bh=(size_t)((b<<4)+h);
    float4 qv, kv;
    qv.x=totf(sm[(d0+0)*49+h]);    qv.y=totf(sm[(d0+1)*49+h]);
    qv.z=totf(sm[(d0+2)*49+h]);    qv.w=totf(sm[(d0+3)*49+h]);
    kv.x=totf(sm[(d0+0)*49+16+h]); kv.y=totf(sm[(d0+1)*49+16+h]);
    kv.z=totf(sm[(d0+2)*49+16+h]); kv.w=totf(sm[(d0+3)*49+16+h]);
    *(float4*)&g_q[stream][(bh*1024+t)*64 + d0] = qv;
    *(float4*)&g_k[stream][(bh*1024+t)*64 + d0] = kv;
#pragma unroll
    for (int j=0;j<4;j++)
        g_vt[stream][bh*65536 + (size_t)(d0+j)*1024 + t] = totf(sm[(d0+j)*49+32+h]);
}

// ---------------- flash cross-attention with tf32 mma ----------------
// dynamic smem: Ks[64*KSTR] | Vs[64*KSTR] | Ps[4][16*PSTR]
#define KSTR 68
#define PSTR 68
#define ATTN_SMEM ((64*KSTR*2 + 4*16*PSTR)*4)
__global__ void __launch_bounds__(128) attn_kernel(){
    extern __shared__ __align__(16) float smdyn[];
    float* Ks = smdyn;
    float* Vs = smdyn + 64*KSTR;
    float* Ps = smdyn + 2*64*KSTR;                  // + w*16*PSTR per warp
    const int tid=threadIdx.x, lane=tid&31, w=tid>>5;
    const int o=blockIdx.z, bh=blockIdx.y, q0=blockIdx.x<<6;
    const int b=bh>>4, h=bh&15;
    const float* qp=g_q [1-o]+(size_t)bh*65536;
    const float* kp=g_k [o]  +(size_t)bh*65536;
    const float* vp=g_vt[o]  +(size_t)bh*65536;
    const int g=lane>>2, tq=lane&3, sel=lane>>3;
    const int aRow=(lane&7)+((sel&1)<<3), aCol=(sel>>1)<<2;
    const int bRow=(lane&7)+((sel>>1)<<3), bCol=(sel&1)<<2;
    uint32_t sK=(uint32_t)__cvta_generic_to_shared(Ks);
    uint32_t sV=(uint32_t)__cvta_generic_to_shared(Vs);
    uint32_t sP=(uint32_t)__cvta_generic_to_shared(Ps + w*16*PSTR);
    float* Pw = Ps + w*16*PSTR;

    // stage Q through Ks, lift warp's 16x64 tile into 8 A-frags (registers)
    for (int i=tid;i<1024;i+=128){ int r=i>>4, c=(i&15)<<2;
        *(float4*)&Ks[r*KSTR+c] = *(const float4*)&qp[(size_t)(q0+r)*64+c]; }
    __syncthreads();
    uint32_t qf[8][4];
#pragma unroll
    for (int kh=0;kh<8;kh++)
        ldsm4(qf[kh], sK + (uint32_t)(((w*16+aRow)*KSTR + kh*8 + aCol)*4));
    __syncthreads();

    float m0=-CUDART_INF_F, m1=-CUDART_INF_F, l0=0.f, l1=0.f;
    float oa[8][4];
#pragma unroll
    for (int i=0;i<8;i++){ oa[i][0]=0;oa[i][1]=0;oa[i][2]=0;oa[i][3]=0; }
    const float sc = 0.125f*1.4426950408889634f;    // 1/sqrt(64) * log2(e)

    for (int t0=0;t0<1024;t0+=64){
        for (int i=tid;i<1024;i+=128){ int r=i>>4, c=(i&15)<<2;
            *(float4*)&Ks[r*KSTR+c] = *(const float4*)&kp[(size_t)(t0+r)*64+c];
            *(float4*)&Vs[r*KSTR+c] = *(const float4*)&vp[(size_t)r*1024 + t0 + c]; }
        __syncthreads();

        // S = Q K^T (16 x 64 per warp)
        float s[8][4];
#pragma unroll
        for (int i=0;i<8;i++){ s[i][0]=0;s[i][1]=0;s[i][2]=0;s[i][3]=0; }
#pragma unroll
        for (int kh=0;kh<8;kh++){
            uint32_t bf[8][2];
#pragma unroll
            for (int f2=0;f2<4;f2++){
                uint32_t r[4];
                ldsm4(r, sK + (uint32_t)(((f2*16+bRow)*KSTR + kh*8 + bCol)*4));
                bf[2*f2][0]=r[0]; bf[2*f2][1]=r[1]; bf[2*f2+1][0]=r[2]; bf[2*f2+1][1]=r[3];
            }
#pragma unroll
            for (int fn=0;fn<8;fn++) mma8(s[fn], qf[kh], bf[fn]);
        }

        // online softmax (rows g and g+8); quad = lanes sharing a row
        float mx0=-CUDART_INF_F, mx1=-CUDART_INF_F;
#pragma unroll
        for (int fn=0;fn<8;fn++){
            s[fn][0]*=sc; s[fn][1]*=sc; s[fn][2]*=sc; s[fn][3]*=sc;
            mx0=fmaxf(mx0,fmaxf(s[fn][0],s[fn][1]));
            mx1=fmaxf(mx1,fmaxf(s[fn][2],s[fn][3]));
        }
        mx0=fmaxf(mx0,__shfl_xor_sync(~0u,mx0,1)); mx0=fmaxf(mx0,__shfl_xor_sync(~0u,mx0,2));
        mx1=fmaxf(mx1,__shfl_xor_sync(~0u,mx1,1)); mx1=fmaxf(mx1,__shfl_xor_sync(~0u,mx1,2));
        float mn0=fmaxf(m0,mx0), mn1=fmaxf(m1,mx1);
        float c0=ex2(m0-mn0), c1=ex2(m1-mn1);
        m0=mn0; m1=mn1;
        float rs0=0.f, rs1=0.f;
#pragma unroll
        for (int fn=0;fn<8;fn++){
            s[fn][0]=ex2(s[fn][0]-mn0); s[fn][1]=ex2(s[fn][1]-mn0);
            s[fn][2]=ex2(s[fn][2]-mn1); s[fn][3]=ex2(s[fn][3]-mn1);
            rs0+=s[fn][0]+s[fn][1]; rs1+=s[fn][2]+s[fn][3];
        }
        rs0+=__shfl_xor_sync(~0u,rs0,1); rs0+=__shfl_xor_sync(~0u,rs0,2);
        rs1+=__shfl_xor_sync(~0u,rs1,1); rs1+=__shfl_xor_sync(~0u,rs1,2);
        l0=l0*c0+rs0; l1=l1*c1+rs1;
#pragma unroll
        for (int fd=0;fd<8;fd++){ oa[fd][0]*=c0; oa[fd][1]*=c0; oa[fd][2]*=c1; oa[fd][3]*=c1; }

        // stage P (tf32) through per-warp smem (16 x 64, stride PSTR), re-read as A-frags
#pragma unroll
        for (int fn=0;fn<8;fn++){
            *(float2*)&Pw[ g   *PSTR + fn*8 + 2*tq] = make_float2(totf(s[fn][0]),totf(s[fn][1]));
            *(float2*)&Pw[(g+8)*PSTR + fn*8 + 2*tq] = make_float2(totf(s[fn][2]),totf(s[fn][3]));
        }
        __syncwarp();

        // O += P V   (B-frags from transposed V: Vs[d][tok])
#pragma unroll
        for (int kh=0;kh<8;kh++){
            uint32_t pf[4];
            ldsm4(pf, sP + (uint32_t)((aRow*PSTR + kh*8 + aCol)*4));
            uint32_t vb[8][2];
#pragma unroll
            for (int f2=0;f2<4;f2++){
                uint32_t r[4];
                ldsm4(r, sV + (uint32_t)(((f2*16+bRow)*KSTR + kh*8 + bCol)*4));
                vb[2*f2][0]=r[0]; vb[2*f2][1]=r[1]; vb[2*f2+1][0]=r[2]; vb[2*f2+1][1]=r[3];
            }
#pragma unroll
            for (int fd=0;fd<8;fd++) mma8(oa[fd], pf, vb[fd]);
        }
        __syncthreads();
    }

    const float i0=1.f/l0, i1=1.f/l1;
    float* ctxp = g_ctx[o];
    const int r0=q0+w*16+g, r1=r0+8;
#pragma unroll
    for (int fd=0;fd<8;fd++){
        int col=(h<<6)+fd*8+2*tq;
        *(float2*)&ctxp[(size_t)((b<<10)+r0)*1024+col] =
            make_float2(totf(oa[fd][0]*i0), totf(oa[fd][1]*i0));
        *(float2*)&ctxp[(size_t)((b<<10)+r1)*1024+col] =
            make_float2(totf(oa[fd][2]*i1), totf(oa[fd][3]*i1));
    }
}

// ---------------------------------------------------------------------------
extern "C" void kernel_launch(void* const* d_in, const int* in_sizes, int n_in,
                              void* d_out, int out_size)
{
    const float* x  =(const float*)d_in[0];
    const float* y  =(const float*)d_in[1];
    const float* W1 =(const float*)d_in[2];
    const float* W2 =(const float*)d_in[3];
    const float* Wo1=(const float*)d_in[4];
    const float* Wo2=(const float*)d_in[5];
    float* out=(float*)d_out;

    cudaFuncSetAttribute(attn_kernel,
                         cudaFuncAttributeMaxDynamicSharedMemorySize, ATTN_SMEM);

    cvt_kernel<<<4096,256>>>((const float4*)x,  0, BTC*EE/4);
    cvt_kernel<<<4096,256>>>((const float4*)y,  1, BTC*EE/4);
    cvt_kernel<<<3072,256>>>((const float4*)W1, 2, NQKV*EE/4);
    cvt_kernel<<<3072,256>>>((const float4*)W2, 3, NQKV*EE/4);
    cvt_kernel<<<1024,256>>>((const float4*)Wo1,4, EE*EE/4);
    cvt_kernel<<<1024,256>>>((const float4*)Wo2,5, EE*EE/4);

    mm_kernel<<<dim3(24,32),256>>>(nullptr,0,0);      // qkv1 = x @ Wqkv1^T
    mm_kernel<<<dim3(24,32),256>>>(nullptr,0,1);      // qkv2 = y @ Wqkv2^T
    deint_kernel<<<4096,256>>>(0);
    deint_kernel<<<4096,256>>>(1);
    attn_kernel<<<dim3(16,64,2),128,ATTN_SMEM>>>();
    mm_kernel<<<dim3(8,32),256>>>(out,                 1,0);  // xo @ Wout1^T
    mm_kernel<<<dim3(8,32),256>>>(out+(size_t)BTC*EE,  1,1);  // yo @ Wout2^T
}